// round 13
// baseline (speedup 1.0000x reference)
#include <cuda_runtime.h>
#include <cuda_bf16.h>

// JPEG q=99 luma-only path (chroma provably constant for grayscale-replicated input).
// 2 lanes per 8x8 tile (even/odd butterfly split), 8 lanes per channel, 4 channels/warp.
// Row passes lane-private; column passes via one shfl exchange + parity-indexed 4x4 dots.

#define C1f 0.98078528040323044913f
#define C2f 0.92387953251128675613f
#define C3f 0.83146961230254523708f
#define C4f 0.70710678118654752440f
#define C5f 0.55557023301960222474f
#define C6f 0.38268343236508977173f
#define C7f 0.19509032201612826785f

__constant__ float YQc[64] = {
    16.f, 11.f, 10.f, 16.f, 24.f, 40.f, 51.f, 61.f,
    12.f, 12.f, 14.f, 19.f, 26.f, 58.f, 60.f, 55.f,
    14.f, 13.f, 16.f, 24.f, 40.f, 57.f, 69.f, 56.f,
    14.f, 17.f, 22.f, 29.f, 51.f, 87.f, 80.f, 62.f,
    18.f, 22.f, 37.f, 56.f, 68.f,109.f,103.f, 77.f,
    24.f, 35.f, 55.f, 64.f, 81.f,104.f,113.f, 92.f,
    49.f, 64.f, 78.f, 87.f,103.f,121.f,120.f,101.f,
    72.f, 92.f, 95.f, 98.f,112.f,100.f,103.f, 99.f
};

__device__ __forceinline__ void dct8(const float in[8], float out[8]) {
    float s0 = in[0] + in[7], s1 = in[1] + in[6], s2 = in[2] + in[5], s3 = in[3] + in[4];
    float d0 = in[0] - in[7], d1 = in[1] - in[6], d2 = in[2] - in[5], d3 = in[3] - in[4];
    out[0] = (s0 + s3) + (s1 + s2);
    out[4] = C4f * ((s0 + s3) - (s1 + s2));
    out[2] = C2f*s0 + C6f*s1 - C6f*s2 - C2f*s3;
    out[6] = C6f*s0 - C2f*s1 + C2f*s2 - C6f*s3;
    out[1] = C1f*d0 + C3f*d1 + C5f*d2 + C7f*d3;
    out[3] = C3f*d0 - C7f*d1 - C1f*d2 - C5f*d3;
    out[5] = C5f*d0 - C1f*d1 + C7f*d2 + C3f*d3;
    out[7] = C7f*d0 - C5f*d1 + C3f*d2 - C1f*d3;
}

__device__ __forceinline__ void idct8(const float e[8], float out[8]) {
    float ev0 = e[0] + C2f*e[2] + C4f*e[4] + C6f*e[6];
    float ev1 = e[0] + C6f*e[2] - C4f*e[4] - C2f*e[6];
    float ev2 = e[0] - C6f*e[2] - C4f*e[4] + C2f*e[6];
    float ev3 = e[0] - C2f*e[2] + C4f*e[4] - C6f*e[6];
    float od0 = C1f*e[1] + C3f*e[3] + C5f*e[5] + C7f*e[7];
    float od1 = C3f*e[1] - C7f*e[3] - C1f*e[5] - C5f*e[7];
    float od2 = C5f*e[1] - C1f*e[3] + C7f*e[5] + C3f*e[7];
    float od3 = C7f*e[1] - C5f*e[3] + C3f*e[5] - C1f*e[7];
    out[0] = ev0 + od0;  out[7] = ev0 - od0;
    out[1] = ev1 + od1;  out[6] = ev1 - od1;
    out[2] = ev2 + od2;  out[5] = ev2 - od2;
    out[3] = ev3 + od3;  out[4] = ev3 - od3;
}

#define CH_STRIDE 200     // floats per channel buffer (196 used, float4-aligned)
#define WARPS_BLK 8       // 256 threads; 4 channels per warp

__global__ __launch_bounds__(256, 3)
void jpeg_y_kernel(const float* __restrict__ x, float* __restrict__ out, int nch)
{
    __shared__ float  shd[WARPS_BLK * 4 * CH_STRIDE];   // 25.6 KB, warp-private slices
    __shared__ float  sKe2[16], sKo[16], sKe3[16];
    __shared__ float2 qt[64];                           // [p][k*8+v]

    const int tid  = threadIdx.x;
    const int lane = tid & 31;
    const int wrp  = tid >> 5;
    const int ch   = lane >> 3;          // channel slot within warp (0..3)
    const int sub  = lane & 7;
    const int tile = sub >> 1;           // tile (0..3)
    const int br   = tile >> 1, bc = tile & 1;
    const int p    = sub & 1;            // butterfly parity: 0=sum/even-u, 1=diff/odd-u
    const float sgn = p ? -1.0f : 1.0f;
    const int rbase = p ? 7 : 0;         // tile-row = rbase + rsgn*rl  (lane1 reversed)
    const int rsgn  = p ? -1 : 1;

    // ---- table init (once per block) ----
    {
        constexpr float KE2[16] = {  1.f,  1.f,  1.f,  1.f,
                                     C2f,  C6f, -C6f, -C2f,
                                     C4f, -C4f, -C4f,  C4f,
                                     C6f, -C2f,  C2f, -C6f };
        constexpr float KO [16] = {  C1f,  C3f,  C5f,  C7f,
                                     C3f, -C7f, -C1f, -C5f,
                                     C5f, -C1f,  C7f,  C3f,
                                     C7f, -C5f,  C3f, -C1f };
        constexpr float KE3[16] = {  1.f,  C2f,  C4f,  C6f,
                                     1.f,  C6f, -C4f, -C2f,
                                     1.f, -C6f, -C4f,  C2f,
                                     1.f, -C2f,  C4f, -C6f };
        if (tid < 16) { sKe2[tid] = KE2[tid]; sKo[tid] = KO[tid]; sKe3[tid] = KE3[tid]; }
        if (tid < 64) {
            int pp = tid >> 5, k = (tid >> 3) & 3, v = tid & 7;
            int u = 2 * k + pp;
            float aa = ((u == 0) ? C4f : 1.0f) * ((v == 0) ? C4f : 1.0f);
            float qv = YQc[u * 8 + v] * 0.02f;          // quality-99 factor
            qt[tid] = make_float2(0.25f * aa / qv, qv * aa);
        }
    }

    const int gch0 = (blockIdx.x * WARPS_BLK + wrp) * 4;
    float* sb = shd + wrp * (4 * CH_STRIDE);

    // ---- stage 4 channels (float4 coalesced) ----
    #pragma unroll
    for (int c = 0; c < 4; c++) {
        if (gch0 + c < nch) {
            const float4* xp4 = (const float4*)(x + (size_t)(gch0 + c) * 196);
            float4* s4 = (float4*)(sb + c * CH_STRIDE);
            s4[lane] = xp4[lane];
            if (lane < 17) s4[lane + 32] = xp4[lane + 32];
        }
    }
    __syncthreads();   // tables + staging

    // ---- per-channel min/max (8 lanes/channel, float4 scan + shuffle) ----
    const float* cb = sb + ch * CH_STRIDE;
    float mn = 3.4e38f, mx = -3.4e38f;
    {
        const float4* cb4 = (const float4*)cb;
        #pragma unroll
        for (int k = 0; k < 7; k++) {
            int i = sub + 8 * k;
            if (i < 49) {
                float4 v = cb4[i];
                mn = fminf(mn, fminf(fminf(v.x, v.y), fminf(v.z, v.w)));
                mx = fmaxf(mx, fmaxf(fmaxf(v.x, v.y), fmaxf(v.z, v.w)));
            }
        }
    }
    #pragma unroll
    for (int o = 1; o < 8; o <<= 1) {
        mn = fminf(mn, __shfl_xor_sync(0xffffffffu, mn, o));
        mx = fmaxf(mx, __shfl_xor_sync(0xffffffffu, mx, o));
    }
    const float rng = mx - mn + 1e-5f;
    const float sc  = 255.0f / rng;
    const float off = -mn * sc - 128.0f;   // w = v*sc + off

    // ---- pass 1: row DCT on this lane's 4 tile-rows ----
    float B[32];                     // B[rl*8 + v]
    #pragma unroll
    for (int rl = 0; rl < 4; rl++) {
        int xr  = rbase + rsgn * rl;
        int row = min(max(8 * br + xr - 1, 0), 13);
        float w[8], r[8];
        #pragma unroll
        for (int y = 0; y < 8; y++) {
            int col = min(max(8 * bc + y - 1, 0), 13);
            w[y] = fmaf(cb[row * 14 + col], sc, off);
        }
        dct8(w, r);
        #pragma unroll
        for (int v = 0; v < 8; v++) B[rl * 8 + v] = r[v];
    }

    // ---- pass 2: column butterfly (exchange) + parity dots + quant ----
    {
        // h[i] = recv + sgn*B : lane0 -> s_i, lane1 -> d_i  (lane1 rows reversed)
        #pragma unroll
        for (int i = 0; i < 32; i++) {
            float rv = __shfl_xor_sync(0xffffffffu, B[i], 1);
            B[i] = fmaf(sgn, B[i], rv);
        }
        float K[16];
        const float* Kp = p ? sKo : sKe2;
        #pragma unroll
        for (int i = 0; i < 16; i++) K[i] = Kp[i];

        #pragma unroll
        for (int v = 0; v < 8; v++) {
            float h0 = B[v], h1 = B[8 + v], h2 = B[16 + v], h3 = B[24 + v];
            #pragma unroll
            for (int k = 0; k < 4; k++) {
                float d = K[k*4]*h0 + K[k*4+1]*h1 + K[k*4+2]*h2 + K[k*4+3]*h3;
                float2 t = qt[p * 32 + k * 8 + v];
                float qd = d * t.x;
                float rr = rintf(qd);           // round-half-even == jnp.round
                float dd = qd - rr;
                B[k * 8 + v] = (rr + dd * dd * dd) * t.y;  // coeff u=2k+p, alpha folded
            }
        }
    }

    // ---- pass 3: column IDCT halves (parity dots) + exchange/combine ----
    {
        float K[16];
        const float* Kp = p ? sKo : sKe3;
        #pragma unroll
        for (int i = 0; i < 16; i++) K[i] = Kp[i];

        #pragma unroll
        for (int v = 0; v < 8; v++) {
            float e0 = B[v], e1 = B[8 + v], e2 = B[16 + v], e3 = B[24 + v];
            #pragma unroll
            for (int k = 0; k < 4; k++)
                B[k * 8 + v] = K[k*4]*e0 + K[k*4+1]*e1 + K[k*4+2]*e2 + K[k*4+3]*e3;
        }
        // out_row: lane0 k -> ev_k + od_k (rows 0..3); lane1 k -> ev_k - od_k (rows 7..4)
        #pragma unroll
        for (int i = 0; i < 32; i++) {
            float rv = __shfl_xor_sync(0xffffffffu, B[i], 1);
            B[i] = fmaf(sgn, B[i], rv);
        }
    }

    __syncwarp();   // all window reads done before output overwrites buffer

    // ---- pass 4: row IDCT + crop/clip/denorm -> shared ----
    {
        const float dsc = rng * (1.0f / 255.0f);
        float* cbw = sb + ch * CH_STRIDE;
        #pragma unroll
        for (int rl = 0; rl < 4; rl++) {
            int xr = rbase + rsgn * rl;
            int i  = 8 * br + xr - 1;
            float e[8], pr[8];
            #pragma unroll
            for (int v = 0; v < 8; v++) e[v] = B[rl * 8 + v];
            idct8(e, pr);
            if ((unsigned)i < 14u) {
                #pragma unroll
                for (int y = 0; y < 8; y++) {
                    int j = 8 * bc + y - 1;
                    if ((unsigned)j < 14u) {
                        float pv = 0.25f * pr[y] + 128.0f;
                        pv = fminf(fmaxf(pv, 0.0f), 255.0f);
                        cbw[i * 14 + j] = pv * dsc + mn;
                    }
                }
            }
        }
    }
    __syncwarp();

    // ---- de-stage 4 channels (float4 coalesced) ----
    #pragma unroll
    for (int c = 0; c < 4; c++) {
        if (gch0 + c < nch) {
            float4* op4 = (float4*)(out + (size_t)(gch0 + c) * 196);
            const float4* s4 = (const float4*)(sb + c * CH_STRIDE);
            op4[lane] = s4[lane];
            if (lane < 17) op4[lane + 32] = s4[lane + 32];
        }
    }
}

extern "C" void kernel_launch(void* const* d_in, const int* in_sizes, int n_in,
                              void* d_out, int out_size)
{
    const float* x = (const float*)d_in[0];
    float* out = (float*)d_out;
    int nch = in_sizes[0] / 196;                 // 32*1024 channels of 14x14
    int chb = WARPS_BLK * 4;                     // 32 channels per block
    int blocks = (nch + chb - 1) / chb;          // 1024
    jpeg_y_kernel<<<blocks, 256>>>(x, out, nch);
}

// round 16
// speedup vs baseline: 1.3249x; 1.3249x over previous
#include <cuda_runtime.h>
#include <cuda_bf16.h>

// JPEG q=99 luma-only path (chroma provably constant for grayscale-replicated input).
// Thread-per-8x8-tile, register transforms with literal constants, warp-autonomous.
// CH_STRIDE=197 (odd): window LDS and output STS provably bank-conflict-free.

#define C1f 0.98078528040323044913f
#define C2f 0.92387953251128675613f
#define C3f 0.83146961230254523708f
#define C4f 0.70710678118654752440f
#define C5f 0.55557023301960222474f
#define C6f 0.38268343236508977173f
#define C7f 0.19509032201612826785f

__device__ __forceinline__ void dct8(const float in[8], float out[8]) {
    float s0 = in[0] + in[7], s1 = in[1] + in[6], s2 = in[2] + in[5], s3 = in[3] + in[4];
    float d0 = in[0] - in[7], d1 = in[1] - in[6], d2 = in[2] - in[5], d3 = in[3] - in[4];
    out[0] = (s0 + s3) + (s1 + s2);
    out[4] = C4f * ((s0 + s3) - (s1 + s2));
    out[2] = C2f*s0 + C6f*s1 - C6f*s2 - C2f*s3;
    out[6] = C6f*s0 - C2f*s1 + C2f*s2 - C6f*s3;
    out[1] = C1f*d0 + C3f*d1 + C5f*d2 + C7f*d3;
    out[3] = C3f*d0 - C7f*d1 - C1f*d2 - C5f*d3;
    out[5] = C5f*d0 - C1f*d1 + C7f*d2 + C3f*d3;
    out[7] = C7f*d0 - C5f*d1 + C3f*d2 - C1f*d3;
}

__device__ __forceinline__ void idct8(const float e[8], float out[8]) {
    float ev0 = e[0] + C2f*e[2] + C4f*e[4] + C6f*e[6];
    float ev1 = e[0] + C6f*e[2] - C4f*e[4] - C2f*e[6];
    float ev2 = e[0] - C6f*e[2] - C4f*e[4] + C2f*e[6];
    float ev3 = e[0] - C2f*e[2] + C4f*e[4] - C6f*e[6];
    float od0 = C1f*e[1] + C3f*e[3] + C5f*e[5] + C7f*e[7];
    float od1 = C3f*e[1] - C7f*e[3] - C1f*e[5] - C5f*e[7];
    float od2 = C5f*e[1] - C1f*e[3] + C7f*e[5] + C3f*e[7];
    float od3 = C7f*e[1] - C5f*e[3] + C3f*e[5] - C1f*e[7];
    out[0] = ev0 + od0;  out[7] = ev0 - od0;
    out[1] = ev1 + od1;  out[6] = ev1 - od1;
    out[2] = ev2 + od2;  out[5] = ev2 - od2;
    out[3] = ev3 + od3;  out[4] = ev3 - od3;
}

#define CH_STRIDE 197     // ODD: perfect bank cover for window reads/writes
#define WARPS_BLK 4

__global__ __launch_bounds__(128, 4)
void jpeg_y_kernel(const float* __restrict__ x, float* __restrict__ out, int nch)
{
    constexpr float YQT[64] = {
        16.f, 11.f, 10.f, 16.f, 24.f, 40.f, 51.f, 61.f,
        12.f, 12.f, 14.f, 19.f, 26.f, 58.f, 60.f, 55.f,
        14.f, 13.f, 16.f, 24.f, 40.f, 57.f, 69.f, 56.f,
        14.f, 17.f, 22.f, 29.f, 51.f, 87.f, 80.f, 62.f,
        18.f, 22.f, 37.f, 56.f, 68.f,109.f,103.f, 77.f,
        24.f, 35.f, 55.f, 64.f, 81.f,104.f,113.f, 92.f,
        49.f, 64.f, 78.f, 87.f,103.f,121.f,120.f,101.f,
        72.f, 92.f, 95.f, 98.f,112.f,100.f,103.f, 99.f
    };
    constexpr float AL[8] = { C4f, 1.f, 1.f, 1.f, 1.f, 1.f, 1.f, 1.f };

    __shared__ float shd[WARPS_BLK * 8 * CH_STRIDE];   // 24.6 KB

    const int lane = threadIdx.x & 31;
    const int wrp  = threadIdx.x >> 5;
    const int chs  = lane >> 2;          // channel slot within warp (0..7)
    const int q    = lane & 3;           // quarter for staging; tile for compute
    const int br   = q >> 1, bc = q & 1;
    const int gch  = (blockIdx.x * WARPS_BLK + wrp) * 8 + chs;
    const bool act = gch < nch;
    float* cb = shd + (wrp * 8 + chs) * CH_STRIDE;

    // ---- stage own channel quarter (LDG.128 -> scalar STS) + min/max fold ----
    float mn = 3.4e38f, mx = -3.4e38f;
    if (act) {
        const float4* xg4 = (const float4*)(x + (size_t)gch * 196);
        #pragma unroll
        for (int k = 0; k < 13; k++) {
            int i = q + 4 * k;
            if (i < 49) {
                float4 v = xg4[i];
                cb[4*i+0] = v.x; cb[4*i+1] = v.y; cb[4*i+2] = v.z; cb[4*i+3] = v.w;
                mn = fminf(mn, fminf(fminf(v.x, v.y), fminf(v.z, v.w)));
                mx = fmaxf(mx, fmaxf(fmaxf(v.x, v.y), fmaxf(v.z, v.w)));
            }
        }
    }
    __syncwarp();

    // ---- per-channel min/max (combine the 4 quarter-lanes) ----
    mn = fminf(mn, __shfl_xor_sync(0xffffffffu, mn, 1));
    mx = fmaxf(mx, __shfl_xor_sync(0xffffffffu, mx, 1));
    mn = fminf(mn, __shfl_xor_sync(0xffffffffu, mn, 2));
    mx = fmaxf(mx, __shfl_xor_sync(0xffffffffu, mx, 2));
    const float rng = mx - mn + 1e-5f;
    const float sc  = 255.0f / rng;
    const float off = -mn * sc - 128.0f;     // w = raw*sc + off

    float A[64];

    // ---- pass 1: row DCT (over y) from padded window (conflict-free LDS) ----
    #pragma unroll
    for (int xr = 0; xr < 8; xr++) {
        int row = min(max(8 * br + xr - 1, 0), 13);
        float w[8], r[8];
        #pragma unroll
        for (int y = 0; y < 8; y++) {
            int col = min(max(8 * bc + y - 1, 0), 13);
            w[y] = fmaf(cb[row * 14 + col], sc, off);
        }
        dct8(w, r);
        #pragma unroll
        for (int v = 0; v < 8; v++) A[xr * 8 + v] = r[v];
    }

    // ---- pass 2: column DCT + diff_round quant/dequant (literal fused consts) ----
    #pragma unroll
    for (int v = 0; v < 8; v++) {
        float c[8], d[8];
        #pragma unroll
        for (int xr = 0; xr < 8; xr++) c[xr] = A[xr * 8 + v];
        dct8(c, d);
        #pragma unroll
        for (int u = 0; u < 8; u++) {
            const float aa = AL[u] * AL[v];
            const float qs = YQT[u * 8 + v] * 0.02f;
            const float iq = 0.25f * aa / qs;     // folds to literal
            const float dq = qs * aa;             // folds to literal
            float qd = d[u] * iq;
            float rr = rintf(qd);                 // round-half-even == jnp.round
            float dd = qd - rr;
            A[u * 8 + v] = (rr + dd * dd * dd) * dq;
        }
    }

    // ---- pass 3: IDCT over u (columns) ----
    #pragma unroll
    for (int v = 0; v < 8; v++) {
        float c[8], s[8];
        #pragma unroll
        for (int u = 0; u < 8; u++) c[u] = A[u * 8 + v];
        idct8(c, s);
        #pragma unroll
        for (int xr = 0; xr < 8; xr++) A[xr * 8 + v] = s[xr];
    }

    __syncwarp();    // all window reads complete before output overwrites buffer

    // ---- pass 4: IDCT over v + crop/clip/denorm -> shared (conflict-free STS) ----
    {
        const float dsc = rng * (1.0f / 255.0f);
        #pragma unroll
        for (int xr = 0; xr < 8; xr++) {
            int i = 8 * br + xr - 1;
            if ((unsigned)i < 14u) {
                float e[8], p[8];
                #pragma unroll
                for (int v = 0; v < 8; v++) e[v] = A[xr * 8 + v];
                idct8(e, p);
                #pragma unroll
                for (int y = 0; y < 8; y++) {
                    int j = 8 * bc + y - 1;
                    if ((unsigned)j < 14u) {
                        float pv = 0.25f * p[y] + 128.0f;
                        pv = fminf(fmaxf(pv, 0.0f), 255.0f);
                        cb[i * 14 + j] = pv * dsc + mn;
                    }
                }
            }
        }
    }
    __syncwarp();

    // ---- de-stage own channel quarter (scalar LDS -> STG.128) ----
    if (act) {
        float4* og4 = (float4*)(out + (size_t)gch * 196);
        #pragma unroll
        for (int k = 0; k < 13; k++) {
            int i = q + 4 * k;
            if (i < 49)
                og4[i] = make_float4(cb[4*i+0], cb[4*i+1], cb[4*i+2], cb[4*i+3]);
        }
    }
}

extern "C" void kernel_launch(void* const* d_in, const int* in_sizes, int n_in,
                              void* d_out, int out_size)
{
    const float* x = (const float*)d_in[0];
    float* out = (float*)d_out;
    int nch = in_sizes[0] / 196;                 // 32*1024 channels of 14x14
    int chb = WARPS_BLK * 8;                     // 32 channels per block
    int blocks = (nch + chb - 1) / chb;          // 1024
    jpeg_y_kernel<<<blocks, 128>>>(x, out, nch);
}